// round 8
// baseline (speedup 1.0000x reference)
#include <cuda_runtime.h>
#include <cuda_bf16.h>

#define BB 8
#define FF 128
#define PP 256
#define TT 2048

// warp-autonomous: warp owns 64 ticks x 32 pe-channels (two 32-tick sub-units
// sharing one prefix). No smem, no barriers.
__global__ __launch_bounds__(128, 7)
void flash_reco_kernel(const float* __restrict__ pe,     // [B,F,P]
                       const float* __restrict__ ftime,  // [B,F]
                       const float* __restrict__ conf,   // [B,F]
                       const float* __restrict__ sigma_ptr,
                       float* __restrict__ out)          // [B,P,T]
{
    const int lane = threadIdx.x & 31;
    const int warp = threadIdx.x >> 5;
    const int b    = blockIdx.z;
    const int p0   = blockIdx.y * 32;
    const int t0   = (blockIdx.x * 4 + warp) * 64;       // 64 ticks per warp

    const float sigma = sigma_ptr ? __ldg(sigma_ptr) : 1.0f;
    const float inv_s = 1.0f / sigma;
    const float W     = 7.0f * sigma;             // exp(-24.5) ~ 2e-11: negligible
    // full-lattice Gaussian sum for interior flashes: sigma*sqrt(2*pi),
    // theta-function correction < e^(-2*pi^2*sigma^2) (2.7e-9 at sigma=1)
    const float inv_anorm = 1.0f / (sigma * 2.5066282746310002f + 1e-10f);
    const bool  analytic_ok = (sigma >= 0.9f);

    // ---- prefix (loaded ONCE, reused for both sub-windows) ----
    float4 tb4 = __ldg(reinterpret_cast<const float4*>(ftime + b * FF) + lane);
    float4 cf4 = __ldg(reinterpret_cast<const float4*>(conf  + b * FF) + lane);
    float tbs[4], cfs[4];
    tbs[0] = fminf(fmaxf(tb4.x * (float)TT, 0.0f), (float)(TT - 1));
    tbs[1] = fminf(fmaxf(tb4.y * (float)TT, 0.0f), (float)(TT - 1));
    tbs[2] = fminf(fmaxf(tb4.z * (float)TT, 0.0f), (float)(TT - 1));
    tbs[3] = fminf(fmaxf(tb4.w * (float)TT, 0.0f), (float)(TT - 1));
    cfs[0] = cf4.x; cfs[1] = cf4.y; cfs[2] = cf4.z; cfs[3] = cf4.w;

    const float* __restrict__ base = pe + (size_t)(b * FF) * PP + p0;

    // ---- union-window prefetch: overlap all row round-trips with setup ----
    {
        const float ulo = (float)t0 - W;
        const float uhi = (float)(t0 + 63) + W;
        #pragma unroll
        for (int j = 0; j < 4; ++j) {
            if (tbs[j] >= ulo && tbs[j] <= uhi) {
                const float* row = base + (4 * lane + j) * PP;   // one 128B line
                asm volatile("prefetch.global.L1 [%0];" :: "l"(row));
            }
        }
    }

    // ---- two 32-tick sub-units sharing the prefix ----
    #pragma unroll
    for (int sub = 0; sub < 2; ++sub) {
        const int   ts  = t0 + sub * 32;
        const float t_f = (float)(ts + lane);
        const float wlo = (float)ts - W;
        const float whi = (float)(ts + 31) + W;

        unsigned long long acc[16];               // 16 packed f32x2 = 32 p's
        #pragma unroll
        for (int j = 0; j < 16; ++j) acc[j] = 0ull;

        #pragma unroll
        for (int j = 0; j < 4; ++j) {
            unsigned mask =
                __ballot_sync(0xffffffffu, tbs[j] >= wlo && tbs[j] <= whi);
            while (mask) {                        // ascending f: deterministic
                const int k = __ffs(mask) - 1;
                mask &= mask - 1;
                const float tbk = __shfl_sync(0xffffffffu, tbs[j], k);
                const float cfk = __shfl_sync(0xffffffffu, cfs[j], k);

                // normalizer: warp-uniform branch (tbk uniform across lanes)
                float csk;
                if (analytic_ok && tbk >= W && tbk <= (float)(TT - 1) - W) {
                    csk = cfk * inv_anorm;
                } else {                          // edge / small-sigma: cooperative
                    const int lo = max(0, (int)ceilf(tbk - W));
                    const int hi = min(TT - 1, (int)floorf(tbk + W));
                    float s = 0.0f;
                    for (int t = lo + lane; t <= hi; t += 32) {
                        const float zz = ((float)t - tbk) * inv_s;
                        s += __expf(-0.5f * zz * zz);
                    }
                    #pragma unroll
                    for (int d = 16; d > 0; d >>= 1)
                        s += __shfl_xor_sync(0xffffffffu, s, d);
                    csk = cfk / (s + 1e-10f);
                }

                const float z = (t_f - tbk) * inv_s;
                const float w = csk * __expf(-0.5f * z * z);
                unsigned long long ww;
                asm("mov.b64 %0, {%1, %1};" : "=l"(ww) : "f"(w));

                const ulonglong2* row = reinterpret_cast<const ulonglong2*>(
                    base + (4 * k + j) * PP);     // uniform broadcast, L1-hot
                #pragma unroll
                for (int q = 0; q < 8; ++q) {
                    ulonglong2 v = __ldg(&row[q]);
                    asm("fma.rn.f32x2 %0, %1, %2, %0;"
                        : "+l"(acc[2 * q])     : "l"(ww), "l"(v.x));
                    asm("fma.rn.f32x2 %0, %1, %2, %0;"
                        : "+l"(acc[2 * q + 1]) : "l"(ww), "l"(v.y));
                }
            }
        }

        // stores: lanes span contiguous t -> coalesced 128B warp stores
        float* op = out + (size_t)(b * PP + p0) * TT + ts + lane;
        #pragma unroll
        for (int j = 0; j < 16; ++j) {
            float lo, hi;
            asm("mov.b64 {%0, %1}, %2;" : "=f"(lo), "=f"(hi) : "l"(acc[j]));
            op[(size_t)(2 * j)     * TT] = lo;
            op[(size_t)(2 * j + 1) * TT] = hi;
        }
    }
}

extern "C" void kernel_launch(void* const* d_in, const int* in_sizes, int n_in,
                              void* d_out, int out_size)
{
    const float* pe = (const float*)d_in[0];           // flashes_pe [B,F,P]
    const float* tm = (const float*)d_in[1];           // flashes_time [B,F,1]
    const float* cf = (const float*)d_in[2];           // flashes_confidence [B,F,1]
    const float* sg = (n_in >= 4) ? (const float*)d_in[n_in - 1] : nullptr;  // sigma last

    dim3 grid(TT / 256, PP / 32, BB);                  // 8 x 8 x 8 = 512 blocks
    flash_reco_kernel<<<grid, 128>>>(pe, tm, cf, sg, (float*)d_out);
}

// round 9
// speedup vs baseline: 1.2063x; 1.2063x over previous
#include <cuda_runtime.h>
#include <cuda_bf16.h>

#define BB 8
#define FF 128
#define PP 256
#define TT 2048

// warp-autonomous: warp owns 32 ticks x 32 pe-channels. No smem, no barriers.
// Block-cooperative unconditional prefetch warms ALL 128 pe rows at this p0
// while the prefix round-trip is in flight -> compute-loop loads are L1 hits.
__global__ __launch_bounds__(128, 7)
void flash_reco_kernel(const float* __restrict__ pe,     // [B,F,P]
                       const float* __restrict__ ftime,  // [B,F]
                       const float* __restrict__ conf,   // [B,F]
                       const float* __restrict__ sigma_ptr,
                       float* __restrict__ out)          // [B,P,T]
{
    const int lane = threadIdx.x & 31;
    const int warp = threadIdx.x >> 5;
    const int b    = blockIdx.z;
    const int p0   = blockIdx.y * 32;
    const int t0   = blockIdx.x * 128 + warp * 32;

    const float* __restrict__ base = pe + (size_t)(b * FF) * PP + p0;

    // ---- unconditional cooperative prefetch: 128 rows / block, 1 line/thread.
    // Issued first; independent of everything -> overlaps the prefix RT.
    asm volatile("prefetch.global.L1 [%0];"
                 :: "l"(base + (warp * 32 + lane) * PP));

    const float sigma = sigma_ptr ? __ldg(sigma_ptr) : 1.0f;
    const float inv_s = 1.0f / sigma;
    const float W     = 7.0f * sigma;             // exp(-24.5) ~ 2e-11: negligible
    // full-lattice Gaussian sum for interior flashes: sigma*sqrt(2*pi),
    // theta-function correction < e^(-2*pi^2*sigma^2) (2.7e-9 at sigma=1)
    const float inv_anorm = 1.0f / (sigma * 2.5066282746310002f + 1e-10f);
    const bool  analytic_ok = (sigma >= 0.9f);

    // ---- prefix: vectorized, lane owns f = 4*lane+j ----
    float4 tb4 = __ldg(reinterpret_cast<const float4*>(ftime + b * FF) + lane);
    float4 cf4 = __ldg(reinterpret_cast<const float4*>(conf  + b * FF) + lane);
    float tbs[4], cfs[4], css[4];
    tbs[0] = fminf(fmaxf(tb4.x * (float)TT, 0.0f), (float)(TT - 1));
    tbs[1] = fminf(fmaxf(tb4.y * (float)TT, 0.0f), (float)(TT - 1));
    tbs[2] = fminf(fmaxf(tb4.z * (float)TT, 0.0f), (float)(TT - 1));
    tbs[3] = fminf(fmaxf(tb4.w * (float)TT, 0.0f), (float)(TT - 1));
    cfs[0] = cf4.x; cfs[1] = cf4.y; cfs[2] = cf4.z; cfs[3] = cf4.w;
    #pragma unroll
    for (int j = 0; j < 4; ++j)
        css[j] = cfs[j] * inv_anorm;              // analytic normalizer, off-chain

    const float t_f = (float)(t0 + lane);
    const float wlo = (float)t0 - W;
    const float whi = (float)(t0 + 31) + W;

    unsigned long long acc[16];                   // 16 packed f32x2 = 32 p's
    #pragma unroll
    for (int j = 0; j < 16; ++j) acc[j] = 0ull;

    #pragma unroll
    for (int j = 0; j < 4; ++j) {
        unsigned mask =
            __ballot_sync(0xffffffffu, tbs[j] >= wlo && tbs[j] <= whi);
        while (mask) {                            // ascending f: deterministic
            const int k = __ffs(mask) - 1;
            mask &= mask - 1;
            const float tbk = __shfl_sync(0xffffffffu, tbs[j], k);

            // normalizer: warp-uniform branch (tbk uniform across lanes)
            float csk;
            if (analytic_ok && tbk >= W && tbk <= (float)(TT - 1) - W) {
                csk = __shfl_sync(0xffffffffu, css[j], k);   // precomputed
            } else {                              // edge / small-sigma: cooperative
                const float cfk = __shfl_sync(0xffffffffu, cfs[j], k);
                const int lo = max(0, (int)ceilf(tbk - W));
                const int hi = min(TT - 1, (int)floorf(tbk + W));
                float s = 0.0f;
                for (int t = lo + lane; t <= hi; t += 32) {
                    const float zz = ((float)t - tbk) * inv_s;
                    s += __expf(-0.5f * zz * zz);
                }
                #pragma unroll
                for (int d = 16; d > 0; d >>= 1)
                    s += __shfl_xor_sync(0xffffffffu, s, d);
                csk = cfk / (s + 1e-10f);
            }

            const float z = (t_f - tbk) * inv_s;
            const float w = csk * __expf(-0.5f * z * z);
            unsigned long long ww;
            asm("mov.b64 %0, {%1, %1};" : "=l"(ww) : "f"(w));

            const ulonglong2* row = reinterpret_cast<const ulonglong2*>(
                base + (4 * k + j) * PP);         // uniform broadcast, L1-warm
            #pragma unroll
            for (int q = 0; q < 8; ++q) {
                ulonglong2 v = __ldg(&row[q]);
                asm("fma.rn.f32x2 %0, %1, %2, %0;"
                    : "+l"(acc[2 * q])     : "l"(ww), "l"(v.x));
                asm("fma.rn.f32x2 %0, %1, %2, %0;"
                    : "+l"(acc[2 * q + 1]) : "l"(ww), "l"(v.y));
            }
        }
    }

    // ---- stores: lanes span contiguous t -> coalesced 128B warp stores ----
    float* op = out + (size_t)(b * PP + p0) * TT + t0 + lane;
    #pragma unroll
    for (int j = 0; j < 16; ++j) {
        float lo, hi;
        asm("mov.b64 {%0, %1}, %2;" : "=f"(lo), "=f"(hi) : "l"(acc[j]));
        op[(size_t)(2 * j)     * TT] = lo;
        op[(size_t)(2 * j + 1) * TT] = hi;
    }
}

extern "C" void kernel_launch(void* const* d_in, const int* in_sizes, int n_in,
                              void* d_out, int out_size)
{
    const float* pe = (const float*)d_in[0];           // flashes_pe [B,F,P]
    const float* tm = (const float*)d_in[1];           // flashes_time [B,F,1]
    const float* cf = (const float*)d_in[2];           // flashes_confidence [B,F,1]
    const float* sg = (n_in >= 4) ? (const float*)d_in[n_in - 1] : nullptr;  // sigma last

    dim3 grid(TT / 128, PP / 32, BB);                  // 16 x 8 x 8 = 1024 blocks
    flash_reco_kernel<<<grid, 128>>>(pe, tm, cf, sg, (float*)d_out);
}